// round 1
// baseline (speedup 1.0000x reference)
#include <cuda_runtime.h>
#include <cuda_bf16.h>
#include <math.h>

// Problem constants
#define CB 4
#define CN 1024
#define CD 1024
#define CH 16
#define CHD 64
#define CCOND 256
#define CR (CB*CN)          // 4096 rows
#define CD12 (12*CD)        // 12288

// ---------------------------------------------------------------------------
// Scratch (device globals; no runtime allocation allowed)
// ---------------------------------------------------------------------------
__device__ float g_ada[CR * CD12];                    // 50.3M
__device__ float g_xn[CR * CD];
__device__ float g_qkv[CR * 3 * CD];
__device__ float g_scores[(long)64 * 1024 * 2048];    // 134M (cross-attn size; self uses part)
__device__ float g_attn_o[CR * CD];
__device__ float g_x1[CR * CD];
__device__ float g_qc[CR * CD];
__device__ float g_mem_ln[2 * CR * CD];
__device__ float g_kv[(long)2 * CR * 2 * CD];
__device__ float g_x2[CR * CD];
__device__ float g_h[(long)CR * 4 * CD];

// ---------------------------------------------------------------------------
// Flexible tiled GEMM.
//   C[m,n] = epilogue( alpha * sum_k A[m,k] * B(k,n) )
//   BT=true : B is row-major [Nc,K]  (C = A * B^T)
//   BT=false: B is row-major [K,Nc]  (C = A * B)
// Batch addressing for ptr P: P += (z/innerMod)*SO + (z%innerMod)*SI
// flags: 1=bias[n], 2=gelu(tanh), 4=residual, 8=gate, 16=mask add
// epilogue order: v = alpha*acc; +bias; +mask; gelu; *gate; +res
// ---------------------------------------------------------------------------
template<int BM, int BN, int BK, int TM, int TN, bool BT>
__global__ __launch_bounds__((BM/TM)*(BN/TN))
void gemm_kernel(
    const float* __restrict__ A, int lda, long aSO, long aSI,
    const float* __restrict__ Bp, int ldb, long bSO, long bSI,
    float* __restrict__ C, int ldc, long cSO, long cSI,
    int M, int Nc, int K, int innerMod, float alpha,
    const float* __restrict__ bias,
    const float* __restrict__ res, int ldres,
    const float* __restrict__ gate, int ldgate,
    const float* __restrict__ mask, int ldmask, long maskSO,
    int flags)
{
    constexpr int TX = BN / TN;
    constexpr int TY = BM / TM;
    constexpr int THREADS = TX * TY;

    __shared__ float As[BK][BM + 4];
    __shared__ float Bs[BK][BN + 4];

    int z  = blockIdx.z;
    int bo = z / innerMod;
    int bi = z % innerMod;
    A  += bo * aSO + bi * aSI;
    Bp += bo * bSO + bi * bSI;
    C  += bo * cSO + bi * cSI;
    if (mask) mask += bo * maskSO;

    int m0 = blockIdx.y * BM;
    int n0 = blockIdx.x * BN;
    int tid = threadIdx.x;
    int tm0 = (tid / TX) * TM;
    int tn0 = (tid % TX) * TN;

    float acc[TM][TN];
    #pragma unroll
    for (int i = 0; i < TM; i++)
        #pragma unroll
        for (int j = 0; j < TN; j++) acc[i][j] = 0.f;

    for (int k0 = 0; k0 < K; k0 += BK) {
        // Load A tile (row-major, K contiguous) -> As[k][m]
        #pragma unroll
        for (int i = tid; i < BM * BK; i += THREADS) {
            int r = i / BK, kk = i % BK;
            int gm = m0 + r, gk = k0 + kk;
            float v = 0.f;
            if (gm < M && gk < K) v = A[(long)gm * lda + gk];
            As[kk][r] = v;
        }
        // Load B tile
        if (BT) {
            #pragma unroll
            for (int i = tid; i < BN * BK; i += THREADS) {
                int r = i / BK, kk = i % BK;
                int gn = n0 + r, gk = k0 + kk;
                float v = 0.f;
                if (gn < Nc && gk < K) v = Bp[(long)gn * ldb + gk];
                Bs[kk][r] = v;
            }
        } else {
            #pragma unroll
            for (int i = tid; i < BN * BK; i += THREADS) {
                int kk = i / BN, c = i % BN;
                int gn = n0 + c, gk = k0 + kk;
                float v = 0.f;
                if (gn < Nc && gk < K) v = Bp[(long)gk * ldb + gn];
                Bs[kk][c] = v;
            }
        }
        __syncthreads();

        #pragma unroll
        for (int kk = 0; kk < BK; kk++) {
            float a[TM], b[TN];
            #pragma unroll
            for (int i = 0; i < TM; i++) a[i] = As[kk][tm0 + i];
            #pragma unroll
            for (int j = 0; j < TN; j++) b[j] = Bs[kk][tn0 + j];
            #pragma unroll
            for (int i = 0; i < TM; i++)
                #pragma unroll
                for (int j = 0; j < TN; j++)
                    acc[i][j] += a[i] * b[j];
        }
        __syncthreads();
    }

    // Epilogue
    #pragma unroll
    for (int i = 0; i < TM; i++) {
        int m = m0 + tm0 + i;
        if (m >= M) continue;
        #pragma unroll
        for (int j = 0; j < TN; j++) {
            int n = n0 + tn0 + j;
            if (n >= Nc) continue;
            float v = alpha * acc[i][j];
            if (flags & 1)  v += bias[n];
            if (flags & 16) v += mask[(long)m * ldmask + n];
            if (flags & 2) {
                float t = v;
                v = 0.5f * t * (1.f + tanhf(0.7978845608028654f * (t + 0.044715f * t * t * t)));
            }
            if (flags & 8)  v *= gate[(long)m * ldgate + n];
            if (flags & 4)  v += res[(long)m * ldres + n];
            C[(long)m * ldc + n] = v;
        }
    }
}

// ---------------------------------------------------------------------------
// Fused LayerNorm (+ optional adaLN modulate). One block per row, D=1024.
// out_row = (b*outSeq + outOff + s) where in row = b*inSeq + s
// ---------------------------------------------------------------------------
__global__ void ln_mod_kernel(
    const float* __restrict__ x, const float* __restrict__ w,
    const float* __restrict__ ada, int adaLd, int shOff, int scOff,
    float* __restrict__ out, int inSeq, int outSeq, int outOff, int hasMod)
{
    int row = blockIdx.x;
    int b = row / inSeq, s = row % inSeq;
    long orow = (long)b * outSeq + outOff + s;
    const float* xi = x + (long)row * CD;
    float* xo = out + orow * CD;
    int tid = threadIdx.x;

    float sum = 0.f, sq = 0.f;
    for (int c = tid; c < CD; c += blockDim.x) {
        float v = xi[c];
        sum += v; sq += v * v;
    }
    __shared__ float s1[256], s2[256];
    s1[tid] = sum; s2[tid] = sq;
    __syncthreads();
    for (int o = 128; o > 0; o >>= 1) {
        if (tid < o) { s1[tid] += s1[tid + o]; s2[tid] += s2[tid + o]; }
        __syncthreads();
    }
    float mean = s1[0] * (1.f / CD);
    float var  = s2[0] * (1.f / CD) - mean * mean;
    float rstd = rsqrtf(var + 1e-5f);

    for (int c = tid; c < CD; c += blockDim.x) {
        float v = (xi[c] - mean) * rstd * w[c];
        if (hasMod) {
            float sh = ada[(long)row * adaLd + shOff + c];
            float sc = ada[(long)row * adaLd + scOff + c];
            v = v * (1.f + sc) + sh;
        }
        xo[c] = v;
    }
}

// ---------------------------------------------------------------------------
// RoPE in place. grid = num rows, block = H*HD/2 = 512 threads.
// pos = (row % S) % posMod
// ---------------------------------------------------------------------------
__global__ void rope_kernel(float* __restrict__ x, long rowStride,
                            const float* __restrict__ cosb,
                            const float* __restrict__ sinb,
                            int S, int posMod)
{
    int row = blockIdx.x;
    int pos = (row % S) % posMod;
    int t = threadIdx.x;
    int h = t / 32;
    int d = t % 32;
    float* p = x + (long)row * rowStride + h * CHD;
    float c = cosb[pos * CHD + d];
    float s = sinb[pos * CHD + d];
    float x1 = p[d], x2 = p[d + 32];
    p[d]      = x1 * c - x2 * s;
    p[d + 32] = x2 * c + x1 * s;
}

// ---------------------------------------------------------------------------
// Row softmax in place. grid = rows, block = 256, length L.
// ---------------------------------------------------------------------------
__global__ void softmax_kernel(float* __restrict__ p, int L)
{
    float* row = p + (long)blockIdx.x * L;
    int tid = threadIdx.x;
    __shared__ float sm[256];

    float mx = -INFINITY;
    for (int c = tid; c < L; c += 256) mx = fmaxf(mx, row[c]);
    sm[tid] = mx; __syncthreads();
    for (int o = 128; o > 0; o >>= 1) {
        if (tid < o) sm[tid] = fmaxf(sm[tid], sm[tid + o]);
        __syncthreads();
    }
    mx = sm[0];
    __syncthreads();

    float sum = 0.f;
    for (int c = tid; c < L; c += 256) {
        float e = __expf(row[c] - mx);
        row[c] = e;
        sum += e;
    }
    sm[tid] = sum; __syncthreads();
    for (int o = 128; o > 0; o >>= 1) {
        if (tid < o) sm[tid] += sm[tid + o];
        __syncthreads();
    }
    float inv = 1.f / sm[0];
    for (int c = tid; c < L; c += 256) row[c] *= inv;
}

// ---------------------------------------------------------------------------
// Host launch
// ---------------------------------------------------------------------------
extern "C" void kernel_launch(void* const* d_in, const int* in_sizes, int n_in,
                              void* d_out, int out_size)
{
    const float* q_x        = (const float*)d_in[0];
    const float* h_content  = (const float*)d_in[1];
    const float* h_obs      = (const float*)d_in[2];
    const float* t_cond     = (const float*)d_in[3];
    const float* cosb       = (const float*)d_in[4];
    const float* sinb       = (const float*)d_in[5];
    const float* M_QQ       = (const float*)d_in[6];
    const float* M_hyb      = (const float*)d_in[7];
    const float* w_ln_self  = (const float*)d_in[8];
    const float* w_qkv      = (const float*)d_in[9];
    const float* w_self_out = (const float*)d_in[10];
    const float* w_ln_cross = (const float*)d_in[11];
    const float* w_ln_mem   = (const float*)d_in[12];
    const float* w_qproj    = (const float*)d_in[13];
    const float* w_kvproj   = (const float*)d_in[14];
    const float* w_cross_out= (const float*)d_in[15];
    const float* w_ln_mlp   = (const float*)d_in[16];
    const float* w_mlp1     = (const float*)d_in[17];
    const float* b_mlp1     = (const float*)d_in[18];
    const float* w_mlp2     = (const float*)d_in[19];
    const float* b_mlp2     = (const float*)d_in[20];
    const float* w_ada      = (const float*)d_in[21];
    const float* b_ada      = (const float*)d_in[22];
    float* outp = (float*)d_out;

    float *ada, *xn, *qkv, *scores, *attn_o, *x1, *qc, *mem_ln, *kv, *x2, *hbuf;
    cudaGetSymbolAddress((void**)&ada,    g_ada);
    cudaGetSymbolAddress((void**)&xn,     g_xn);
    cudaGetSymbolAddress((void**)&qkv,    g_qkv);
    cudaGetSymbolAddress((void**)&scores, g_scores);
    cudaGetSymbolAddress((void**)&attn_o, g_attn_o);
    cudaGetSymbolAddress((void**)&x1,     g_x1);
    cudaGetSymbolAddress((void**)&qc,     g_qc);
    cudaGetSymbolAddress((void**)&mem_ln, g_mem_ln);
    cudaGetSymbolAddress((void**)&kv,     g_kv);
    cudaGetSymbolAddress((void**)&x2,     g_x2);
    cudaGetSymbolAddress((void**)&hbuf,   g_h);

    const int TPB = 256;

    // 1. ada = t_cond @ w_ada^T + b_ada   [4096 x 12288, K=256]
    gemm_kernel<128,128,8,8,8,true><<<dim3(CD12/128, CR/128, 1), TPB>>>(
        t_cond, CCOND, 0, 0,  w_ada, CCOND, 0, 0,  ada, CD12, 0, 0,
        CR, CD12, CCOND, 1, 1.f,
        b_ada, nullptr, 0, nullptr, 0, nullptr, 0, 0, 1);

    // 2. xn = modulate(LN(q_x), sh_s, sc_s)
    ln_mod_kernel<<<CR, 256>>>(q_x, w_ln_self, ada, CD12, 0*CD, 1*CD,
                               xn, CN, CN, 0, 1);

    // 3. qkv = xn @ w_qkv^T   [4096 x 3072, K=1024]
    gemm_kernel<128,128,8,8,8,true><<<dim3(3*CD/128, CR/128, 1), TPB>>>(
        xn, CD, 0, 0,  w_qkv, CD, 0, 0,  qkv, 3*CD, 0, 0,
        CR, 3*CD, CD, 1, 1.f,
        nullptr, nullptr, 0, nullptr, 0, nullptr, 0, 0, 0);

    // 4. RoPE on q and k slots (in place)
    rope_kernel<<<CR, 512>>>(qkv,      3*CD, cosb, sinb, CN, CN);
    rope_kernel<<<CR, 512>>>(qkv + CD, 3*CD, cosb, sinb, CN, CN);

    // 5. self scores = q @ k^T / 8 + M_QQ  (batched over b,h; K=64)
    gemm_kernel<128,128,8,8,8,true><<<dim3(CN/128, CN/128, CB*CH), TPB>>>(
        qkv,      3*CD, (long)CN*3*CD, CHD,
        qkv + CD, 3*CD, (long)CN*3*CD, CHD,
        scores, CN, (long)CH*CN*CN, (long)CN*CN,
        CN, CN, CHD, CH, 0.125f,
        nullptr, nullptr, 0, nullptr, 0,
        M_QQ, CN, (long)CN*CN, 16);

    // 6. softmax over N
    softmax_kernel<<<CB*CH*CN, 256>>>(scores, CN);

    // 7. O = P @ V   (NN, Nc=64)
    gemm_kernel<64,64,16,4,4,false><<<dim3(1, CN/64, CB*CH), TPB>>>(
        scores, CN, (long)CH*CN*CN, (long)CN*CN,
        qkv + 2*CD, 3*CD, (long)CN*3*CD, CHD,
        attn_o, CD, (long)CN*CD, CHD,
        CN, CHD, CN, CH, 1.f,
        nullptr, nullptr, 0, nullptr, 0, nullptr, 0, 0, 0);

    // 8. x1 = q_x + g_s * (O @ w_self_out^T)
    gemm_kernel<128,128,8,8,8,true><<<dim3(CD/128, CR/128, 1), TPB>>>(
        attn_o, CD, 0, 0,  w_self_out, CD, 0, 0,  x1, CD, 0, 0,
        CR, CD, CD, 1, 1.f,
        nullptr, q_x, CD, ada + 2*CD, CD12, nullptr, 0, 0, 4|8);

    // 9. xn = modulate(LN(x1), sh_c, sc_c)
    ln_mod_kernel<<<CR, 256>>>(x1, w_ln_cross, ada, CD12, 3*CD, 4*CD,
                               xn, CN, CN, 0, 1);

    // 10. qc = xn @ w_qproj^T ; RoPE
    gemm_kernel<128,128,8,8,8,true><<<dim3(CD/128, CR/128, 1), TPB>>>(
        xn, CD, 0, 0,  w_qproj, CD, 0, 0,  qc, CD, 0, 0,
        CR, CD, CD, 1, 1.f,
        nullptr, nullptr, 0, nullptr, 0, nullptr, 0, 0, 0);
    rope_kernel<<<CR, 512>>>(qc, CD, cosb, sinb, CN, CN);

    // 11. mem_ln = LN(concat(h_content, h_obs)) * w_ln_mem
    ln_mod_kernel<<<CR, 256>>>(h_content, w_ln_mem, nullptr, 0, 0, 0,
                               mem_ln, CN, 2*CN, 0, 0);
    ln_mod_kernel<<<CR, 256>>>(h_obs, w_ln_mem, nullptr, 0, 0, 0,
                               mem_ln, CN, 2*CN, CN, 0);

    // 12. kv = mem_ln @ w_kvproj^T   [8192 x 2048, K=1024]
    gemm_kernel<128,128,8,8,8,true><<<dim3(2*CD/128, 2*CR/128, 1), TPB>>>(
        mem_ln, CD, 0, 0,  w_kvproj, CD, 0, 0,  kv, 2*CD, 0, 0,
        2*CR, 2*CD, CD, 1, 1.f,
        nullptr, nullptr, 0, nullptr, 0, nullptr, 0, 0, 0);

    // 13. RoPE on kc (slot 0), positions mod N
    rope_kernel<<<2*CR, 512>>>(kv, 2*CD, cosb, sinb, 2*CN, CN);

    // 14. cross scores = qc @ kc^T / 8 + M_hyb   [1024 x 2048 per (b,h), K=64]
    gemm_kernel<128,128,8,8,8,true><<<dim3(2*CN/128, CN/128, CB*CH), TPB>>>(
        qc, CD, (long)CN*CD, CHD,
        kv, 2*CD, (long)2*CN*2*CD, CHD,
        scores, 2*CN, (long)CH*CN*2*CN, (long)CN*2*CN,
        CN, 2*CN, CHD, CH, 0.125f,
        nullptr, nullptr, 0, nullptr, 0,
        M_hyb, 2*CN, (long)CN*2*CN, 16);

    // 15. softmax over 2N
    softmax_kernel<<<CB*CH*CN, 256>>>(scores, 2*CN);

    // 16. O = P @ Vc
    gemm_kernel<64,64,16,4,4,false><<<dim3(1, CN/64, CB*CH), TPB>>>(
        scores, 2*CN, (long)CH*CN*2*CN, (long)CN*2*CN,
        kv + CD, 2*CD, (long)2*CN*2*CD, CHD,
        attn_o, CD, (long)CN*CD, CHD,
        CN, CHD, 2*CN, CH, 1.f,
        nullptr, nullptr, 0, nullptr, 0, nullptr, 0, 0, 0);

    // 17. x2 = x1 + g_c * (O @ w_cross_out^T)
    gemm_kernel<128,128,8,8,8,true><<<dim3(CD/128, CR/128, 1), TPB>>>(
        attn_o, CD, 0, 0,  w_cross_out, CD, 0, 0,  x2, CD, 0, 0,
        CR, CD, CD, 1, 1.f,
        nullptr, x1, CD, ada + 5*CD, CD12, nullptr, 0, 0, 4|8);

    // 18. xn = modulate(LN(x2), sh_m, sc_m)
    ln_mod_kernel<<<CR, 256>>>(x2, w_ln_mlp, ada, CD12, 6*CD, 7*CD,
                               xn, CN, CN, 0, 1);

    // 19. h = gelu(xn @ w_mlp1^T + b_mlp1)   [4096 x 4096, K=1024]
    gemm_kernel<128,128,8,8,8,true><<<dim3(4*CD/128, CR/128, 1), TPB>>>(
        xn, CD, 0, 0,  w_mlp1, CD, 0, 0,  hbuf, 4*CD, 0, 0,
        CR, 4*CD, CD, 1, 1.f,
        b_mlp1, nullptr, 0, nullptr, 0, nullptr, 0, 0, 1|2);

    // 20. out = x2 + g_m * (h @ w_mlp2^T + b_mlp2)   [4096 x 1024, K=4096]
    gemm_kernel<128,128,8,8,8,true><<<dim3(CD/128, CR/128, 1), TPB>>>(
        hbuf, 4*CD, 0, 0,  w_mlp2, 4*CD, 0, 0,  outp, CD, 0, 0,
        CR, CD, 4*CD, 1, 1.f,
        b_mlp2, x2, CD, ada + 8*CD, CD12, nullptr, 0, 0, 1|4|8);
}

// round 3
// speedup vs baseline: 2.5931x; 2.5931x over previous
#include <cuda_runtime.h>
#include <cuda_bf16.h>
#include <math.h>
#include <stdint.h>

// Problem constants
#define CB 4
#define CN 1024
#define CD 1024
#define CH 16
#define CHD 64
#define CCOND 256
#define CR (CB*CN)          // 4096 rows
#define CD12 (12*CD)        // 12288

// ---------------------------------------------------------------------------
// Scratch (device globals; no runtime allocation allowed)
// ---------------------------------------------------------------------------
__device__ float g_ada[CR * CD12];
__device__ float g_xn[CR * CD];
__device__ float g_qkv[CR * 3 * CD];
__device__ float g_scores[(long)64 * 1024 * 2048];
__device__ float g_attn_o[CR * CD];
__device__ float g_x1[CR * CD];
__device__ float g_qc[CR * CD];
__device__ float g_mem_ln[2 * CR * CD];
__device__ float g_kv[(long)2 * CR * 2 * CD];
__device__ float g_x2[CR * CD];
__device__ float g_h[(long)CR * 4 * CD];
__device__ float g_vt[(long)8 * 1024 * 1024];   // transposed V

// ---------------------------------------------------------------------------
// PTX helpers (baseline features only — harness targets plain sm_100)
// ---------------------------------------------------------------------------
__device__ __forceinline__ uint32_t smem_u32(const void* p) {
    uint32_t a;
    asm("{ .reg .u64 t; cvta.to.shared.u64 t, %1; cvt.u32.u64 %0, t; }" : "=r"(a) : "l"(p));
    return a;
}
__device__ __forceinline__ uint32_t f2tf32(float x) {
    uint32_t u;
    asm("cvt.rna.tf32.f32 %0, %1;" : "=r"(u) : "f"(x));
    return u;
}
__device__ __forceinline__ void cpa16(uint32_t dst, const void* src) {
    asm volatile("cp.async.cg.shared.global [%0], [%1], 16;" :: "r"(dst), "l"(src));
}
#define CP_COMMIT() asm volatile("cp.async.commit_group;" ::: "memory")
#define CP_WAIT(n)  asm volatile("cp.async.wait_group %0;" :: "n"(n) : "memory")

__device__ __forceinline__ void mma8(float* d, const uint32_t* a, const uint32_t* b) {
    asm volatile(
        "mma.sync.aligned.m16n8k8.row.col.f32.tf32.tf32.f32 "
        "{%0,%1,%2,%3}, {%4,%5,%6,%7}, {%8,%9}, {%0,%1,%2,%3};"
        : "+f"(d[0]), "+f"(d[1]), "+f"(d[2]), "+f"(d[3])
        : "r"(a[0]), "r"(a[1]), "r"(a[2]), "r"(a[3]), "r"(b[0]), "r"(b[1]));
}

__device__ __forceinline__ float gelu_t(float t) {
    return 0.5f * t * (1.f + tanhf(0.7978845608028654f * (t + 0.044715f * t * t * t)));
}

// ---------------------------------------------------------------------------
// tf32 mma.sync GEMM.  C[m,n] = epilogue(alpha * sum_k A[m,k]*B[n,k])
// A: [M,K] row-major (lda), B: [Nc,K] row-major (ldb). BM=128, BK=32, 256 thr.
// All dims must be exact multiples (M%128==0, Nc%BN==0, K%32==0) — they are.
// Batch z: ptr += (z/innerMod)*SO + (z%innerMod)*SI
// flags: 1=bias[n], 2=gelu, 4=residual, 8=gate, 16=mask add
// order: v = alpha*acc; +bias; +mask; gelu; *gate; +res
// ---------------------------------------------------------------------------
template<int BN>
__global__ __launch_bounds__(256, 1)
void gemm_mma(
    const float* __restrict__ A, int lda, long aSO, long aSI,
    const float* __restrict__ Bp, int ldb, long bSO, long bSI,
    float* __restrict__ C, int ldc, long cSO, long cSI,
    int M, int Nc, int K, int innerMod, float alpha,
    const float* __restrict__ bias,
    const float* __restrict__ res, int ldres,
    const float* __restrict__ gate, int ldgate,
    const float* __restrict__ mask, int ldmask, long maskSO,
    int flags)
{
    constexpr int NI = BN / 32;            // n-fragments per warp
    constexpr int LDP = 36;                // padded row (floats)
    constexpr int A_FLOATS = 128 * LDP;    // per buffer
    constexpr int B_FLOATS = BN * LDP;

    extern __shared__ float smem[];
    float* sA = smem;                      // [2][128][36]
    float* sB = smem + 2 * A_FLOATS;       // [2][BN][36]
    uint32_t sAu = smem_u32(sA);
    uint32_t sBu = smem_u32(sB);

    int tid = threadIdx.x;
    int wid = tid >> 5, lane = tid & 31;
    int gid = lane >> 2, tg = lane & 3;
    int wm = (wid >> 2) * 64;              // warp m offset in tile
    int wn = (wid & 3) * (BN / 4);         // warp n offset in tile

    int z = blockIdx.z;
    int bo = z / innerMod, bi = z % innerMod;
    A  += bo * aSO + bi * aSI;
    Bp += bo * bSO + bi * bSI;
    C  += bo * cSO + bi * cSI;
    if (mask) mask += bo * maskSO;

    int m0 = blockIdx.y * 128;
    int n0 = blockIdx.x * BN;

    float acc[4][NI][4];
    #pragma unroll
    for (int i = 0; i < 4; i++)
        #pragma unroll
        for (int j = 0; j < NI; j++)
            #pragma unroll
            for (int q = 0; q < 4; q++) acc[i][j][q] = 0.f;

    int nCh = K >> 5;

    auto loadA = [&](int c, int buf) {
        const float* Ab = A + (long)m0 * lda + (c << 5);
        #pragma unroll
        for (int i = 0; i < 4; i++) {
            int idx = tid + i * 256;
            int r = idx >> 3, q = idx & 7;
            cpa16(sAu + (uint32_t)((buf * 128 + r) * LDP + q * 4) * 4,
                  Ab + (long)r * lda + q * 4);
        }
    };
    auto loadB = [&](int c, int buf) {
        const float* Bb = Bp + (long)n0 * ldb + (c << 5);
        #pragma unroll
        for (int i = 0; i < BN / 32; i++) {
            int idx = tid + i * 256;
            int r = idx >> 3, q = idx & 7;
            cpa16(sBu + (uint32_t)((buf * BN + r) * LDP + q * 4) * 4,
                  Bb + (long)r * ldb + q * 4);
        }
    };

    loadA(0, 0); loadB(0, 0); CP_COMMIT();

    for (int c = 0; c < nCh; c++) {
        int buf = c & 1;
        if (c + 1 < nCh) {
            loadA(c + 1, buf ^ 1); loadB(c + 1, buf ^ 1); CP_COMMIT();
            CP_WAIT(1);
        } else {
            CP_WAIT(0);
        }
        __syncthreads();

        const float* Ab = sA + buf * A_FLOATS;
        const float* Bb = sB + buf * B_FLOATS;
        #pragma unroll
        for (int ks = 0; ks < 4; ks++) {
            uint32_t af[4][4];
            #pragma unroll
            for (int mi = 0; mi < 4; mi++) {
                int m = wm + mi * 16 + gid;
                int k = ks * 8 + tg;
                af[mi][0] = f2tf32(Ab[m * LDP + k]);
                af[mi][1] = f2tf32(Ab[(m + 8) * LDP + k]);
                af[mi][2] = f2tf32(Ab[m * LDP + k + 4]);
                af[mi][3] = f2tf32(Ab[(m + 8) * LDP + k + 4]);
            }
            uint32_t bf[NI][2];
            #pragma unroll
            for (int ni = 0; ni < NI; ni++) {
                int n = wn + ni * 8 + gid;
                int k = ks * 8 + tg;
                bf[ni][0] = f2tf32(Bb[n * LDP + k]);
                bf[ni][1] = f2tf32(Bb[n * LDP + k + 4]);
            }
            #pragma unroll
            for (int mi = 0; mi < 4; mi++)
                #pragma unroll
                for (int ni = 0; ni < NI; ni++)
                    mma8(acc[mi][ni], af[mi], bf[ni]);
        }
        __syncthreads();
    }

    // Epilogue: fragments -> fused ops -> float2 stores (32B sectors per row)
    #pragma unroll
    for (int mi = 0; mi < 4; mi++) {
        #pragma unroll
        for (int ni = 0; ni < NI; ni++) {
            int n = n0 + wn + ni * 8 + tg * 2;
            #pragma unroll
            for (int half = 0; half < 2; half++) {
                int m = m0 + wm + mi * 16 + gid + half * 8;
                float a0 = alpha * acc[mi][ni][half * 2];
                float a1 = alpha * acc[mi][ni][half * 2 + 1];
                if (flags & 1) { a0 += bias[n]; a1 += bias[n + 1]; }
                if (flags & 16) {
                    float2 mk = *(const float2*)(mask + (long)m * ldmask + n);
                    a0 += mk.x; a1 += mk.y;
                }
                if (flags & 2) { a0 = gelu_t(a0); a1 = gelu_t(a1); }
                if (flags & 8) {
                    float2 gv = *(const float2*)(gate + (long)m * ldgate + n);
                    a0 *= gv.x; a1 *= gv.y;
                }
                if (flags & 4) {
                    float2 rv = *(const float2*)(res + (long)m * ldres + n);
                    a0 += rv.x; a1 += rv.y;
                }
                *(float2*)(C + (long)m * ldc + n) = make_float2(a0, a1);
            }
        }
    }
}

// ---------------------------------------------------------------------------
// Fused LayerNorm (+ optional adaLN modulate). One block per row, D=1024.
// ---------------------------------------------------------------------------
__global__ void ln_mod_kernel(
    const float* __restrict__ x, const float* __restrict__ w,
    const float* __restrict__ ada, int adaLd, int shOff, int scOff,
    float* __restrict__ out, int inSeq, int outSeq, int outOff, int hasMod)
{
    int row = blockIdx.x;
    int b = row / inSeq, s = row % inSeq;
    long orow = (long)b * outSeq + outOff + s;
    const float* xi = x + (long)row * CD;
    float* xo = out + orow * CD;
    int tid = threadIdx.x;

    float sum = 0.f, sq = 0.f;
    for (int c = tid; c < CD; c += blockDim.x) {
        float v = xi[c];
        sum += v; sq += v * v;
    }
    __shared__ float s1[256], s2[256];
    s1[tid] = sum; s2[tid] = sq;
    __syncthreads();
    for (int o = 128; o > 0; o >>= 1) {
        if (tid < o) { s1[tid] += s1[tid + o]; s2[tid] += s2[tid + o]; }
        __syncthreads();
    }
    float mean = s1[0] * (1.f / CD);
    float var  = s2[0] * (1.f / CD) - mean * mean;
    float rstd = rsqrtf(var + 1e-5f);

    for (int c = tid; c < CD; c += blockDim.x) {
        float v = (xi[c] - mean) * rstd * w[c];
        if (hasMod) {
            float sh = ada[(long)row * adaLd + shOff + c];
            float sc = ada[(long)row * adaLd + scOff + c];
            v = v * (1.f + sc) + sh;
        }
        xo[c] = v;
    }
}

// ---------------------------------------------------------------------------
// RoPE in place. grid = rows, block = 512. pos = (row % S) % posMod
// ---------------------------------------------------------------------------
__global__ void rope_kernel(float* __restrict__ x, long rowStride,
                            const float* __restrict__ cosb,
                            const float* __restrict__ sinb,
                            int S, int posMod)
{
    int row = blockIdx.x;
    int pos = (row % S) % posMod;
    int t = threadIdx.x;
    int h = t / 32;
    int d = t % 32;
    float* p = x + (long)row * rowStride + h * CHD;
    float c = cosb[pos * CHD + d];
    float s = sinb[pos * CHD + d];
    float x1 = p[d], x2 = p[d + 32];
    p[d]      = x1 * c - x2 * s;
    p[d + 32] = x2 * c + x1 * s;
}

// ---------------------------------------------------------------------------
// Row softmax in place. grid = rows, block = 256.
// ---------------------------------------------------------------------------
__global__ void softmax_kernel(float* __restrict__ p, int L)
{
    float* row = p + (long)blockIdx.x * L;
    int tid = threadIdx.x;
    __shared__ float sm[256];

    float mx = -INFINITY;
    for (int c = tid; c < L; c += 256) mx = fmaxf(mx, row[c]);
    sm[tid] = mx; __syncthreads();
    for (int o = 128; o > 0; o >>= 1) {
        if (tid < o) sm[tid] = fmaxf(sm[tid], sm[tid + o]);
        __syncthreads();
    }
    mx = sm[0];
    __syncthreads();

    float sum = 0.f;
    for (int c = tid; c < L; c += 256) {
        float e = __expf(row[c] - mx);
        row[c] = e;
        sum += e;
    }
    sm[tid] = sum; __syncthreads();
    for (int o = 128; o > 0; o >>= 1) {
        if (tid < o) sm[tid] += sm[tid + o];
        __syncthreads();
    }
    float inv = 1.f / sm[0];
    for (int c = tid; c < L; c += 256) row[c] *= inv;
}

// ---------------------------------------------------------------------------
// V transpose: src (z=b*CH+h, k, d) -> dst [z][d][k] (k contiguous)
// ---------------------------------------------------------------------------
__global__ void transpose_v(const float* __restrict__ src, float* __restrict__ dst,
                            int kLen, int srcRow)
{
    __shared__ float t[32][33];
    int z = blockIdx.z;
    int k0 = blockIdx.x * 32, d0 = blockIdx.y * 32;
    const float* s = src + (long)(z / CH) * kLen * srcRow + (z % CH) * CHD;
    int tx = threadIdx.x, ty = threadIdx.y;
    for (int r = ty; r < 32; r += 8)
        t[r][tx] = s[(long)(k0 + r) * srcRow + d0 + tx];
    __syncthreads();
    float* dp = dst + ((long)z * CHD + d0) * kLen + k0;
    for (int r = ty; r < 32; r += 8)
        dp[(long)r * kLen + tx] = t[tx][r];
}

// ---------------------------------------------------------------------------
// Host launch
// ---------------------------------------------------------------------------
extern "C" void kernel_launch(void* const* d_in, const int* in_sizes, int n_in,
                              void* d_out, int out_size)
{
    const float* q_x        = (const float*)d_in[0];
    const float* h_content  = (const float*)d_in[1];
    const float* h_obs      = (const float*)d_in[2];
    const float* t_cond     = (const float*)d_in[3];
    const float* cosb       = (const float*)d_in[4];
    const float* sinb       = (const float*)d_in[5];
    const float* M_QQ       = (const float*)d_in[6];
    const float* M_hyb      = (const float*)d_in[7];
    const float* w_ln_self  = (const float*)d_in[8];
    const float* w_qkv      = (const float*)d_in[9];
    const float* w_self_out = (const float*)d_in[10];
    const float* w_ln_cross = (const float*)d_in[11];
    const float* w_ln_mem   = (const float*)d_in[12];
    const float* w_qproj    = (const float*)d_in[13];
    const float* w_kvproj   = (const float*)d_in[14];
    const float* w_cross_out= (const float*)d_in[15];
    const float* w_ln_mlp   = (const float*)d_in[16];
    const float* w_mlp1     = (const float*)d_in[17];
    const float* b_mlp1     = (const float*)d_in[18];
    const float* w_mlp2     = (const float*)d_in[19];
    const float* b_mlp2     = (const float*)d_in[20];
    const float* w_ada      = (const float*)d_in[21];
    const float* b_ada      = (const float*)d_in[22];
    float* outp = (float*)d_out;

    float *ada, *xn, *qkv, *scores, *attn_o, *x1, *qc, *mem_ln, *kv, *x2, *hbuf, *vt;
    cudaGetSymbolAddress((void**)&ada,    g_ada);
    cudaGetSymbolAddress((void**)&xn,     g_xn);
    cudaGetSymbolAddress((void**)&qkv,    g_qkv);
    cudaGetSymbolAddress((void**)&scores, g_scores);
    cudaGetSymbolAddress((void**)&attn_o, g_attn_o);
    cudaGetSymbolAddress((void**)&x1,     g_x1);
    cudaGetSymbolAddress((void**)&qc,     g_qc);
    cudaGetSymbolAddress((void**)&mem_ln, g_mem_ln);
    cudaGetSymbolAddress((void**)&kv,     g_kv);
    cudaGetSymbolAddress((void**)&x2,     g_x2);
    cudaGetSymbolAddress((void**)&hbuf,   g_h);
    cudaGetSymbolAddress((void**)&vt,     g_vt);

    const int SM128 = (2 * 128 * 36 + 2 * 128 * 36) * 4;  // 73728
    const int SM64  = (2 * 128 * 36 + 2 * 64 * 36) * 4;   // 55296
    cudaFuncSetAttribute(gemm_mma<128>, cudaFuncAttributeMaxDynamicSharedMemorySize, SM128);
    cudaFuncSetAttribute(gemm_mma<64>,  cudaFuncAttributeMaxDynamicSharedMemorySize, SM64);

    // 1. ada = t_cond @ w_ada^T + b_ada
    gemm_mma<128><<<dim3(CD12/128, CR/128, 1), 256, SM128>>>(
        t_cond, CCOND, 0, 0,  w_ada, CCOND, 0, 0,  ada, CD12, 0, 0,
        CR, CD12, CCOND, 1, 1.f,
        b_ada, nullptr, 0, nullptr, 0, nullptr, 0, 0, 1);

    // 2. xn = modulate(LN(q_x), sh_s, sc_s)
    ln_mod_kernel<<<CR, 256>>>(q_x, w_ln_self, ada, CD12, 0*CD, 1*CD,
                               xn, CN, CN, 0, 1);

    // 3. qkv = xn @ w_qkv^T
    gemm_mma<128><<<dim3(3*CD/128, CR/128, 1), 256, SM128>>>(
        xn, CD, 0, 0,  w_qkv, CD, 0, 0,  qkv, 3*CD, 0, 0,
        CR, 3*CD, CD, 1, 1.f,
        nullptr, nullptr, 0, nullptr, 0, nullptr, 0, 0, 0);

    // 4. RoPE on q and k; transpose V
    rope_kernel<<<CR, 512>>>(qkv,      3*CD, cosb, sinb, CN, CN);
    rope_kernel<<<CR, 512>>>(qkv + CD, 3*CD, cosb, sinb, CN, CN);
    transpose_v<<<dim3(CN/32, CHD/32, CB*CH), dim3(32,8)>>>(qkv + 2*CD, vt, CN, 3*CD);

    // 5. self scores = q @ k^T / 8 + M_QQ
    gemm_mma<128><<<dim3(CN/128, CN/128, CB*CH), 256, SM128>>>(
        qkv,      3*CD, (long)CN*3*CD, CHD,
        qkv + CD, 3*CD, (long)CN*3*CD, CHD,
        scores, CN, (long)CH*CN*CN, (long)CN*CN,
        CN, CN, CHD, CH, 0.125f,
        nullptr, nullptr, 0, nullptr, 0,
        M_QQ, CN, (long)CN*CN, 16);

    // 6. softmax
    softmax_kernel<<<CB*CH*CN, 256>>>(scores, CN);

    // 7. O = P @ V (B = vt, K-major)
    gemm_mma<64><<<dim3(1, CN/128, CB*CH), 256, SM64>>>(
        scores, CN, (long)CH*CN*CN, (long)CN*CN,
        vt, CN, (long)CH*CHD*CN, (long)CHD*CN,
        attn_o, CD, (long)CN*CD, CHD,
        CN, CHD, CN, CH, 1.f,
        nullptr, nullptr, 0, nullptr, 0, nullptr, 0, 0, 0);

    // 8. x1 = q_x + g_s * (O @ w_self_out^T)
    gemm_mma<128><<<dim3(CD/128, CR/128, 1), 256, SM128>>>(
        attn_o, CD, 0, 0,  w_self_out, CD, 0, 0,  x1, CD, 0, 0,
        CR, CD, CD, 1, 1.f,
        nullptr, q_x, CD, ada + 2*CD, CD12, nullptr, 0, 0, 4|8);

    // 9. xn = modulate(LN(x1), sh_c, sc_c)
    ln_mod_kernel<<<CR, 256>>>(x1, w_ln_cross, ada, CD12, 3*CD, 4*CD,
                               xn, CN, CN, 0, 1);

    // 10. qc = xn @ w_qproj^T ; RoPE
    gemm_mma<128><<<dim3(CD/128, CR/128, 1), 256, SM128>>>(
        xn, CD, 0, 0,  w_qproj, CD, 0, 0,  qc, CD, 0, 0,
        CR, CD, CD, 1, 1.f,
        nullptr, nullptr, 0, nullptr, 0, nullptr, 0, 0, 0);
    rope_kernel<<<CR, 512>>>(qc, CD, cosb, sinb, CN, CN);

    // 11. mem_ln = LN(concat(h_content, h_obs)) * w_ln_mem
    ln_mod_kernel<<<CR, 256>>>(h_content, w_ln_mem, nullptr, 0, 0, 0,
                               mem_ln, CN, 2*CN, 0, 0);
    ln_mod_kernel<<<CR, 256>>>(h_obs, w_ln_mem, nullptr, 0, 0, 0,
                               mem_ln, CN, 2*CN, CN, 0);

    // 12. kv = mem_ln @ w_kvproj^T
    gemm_mma<128><<<dim3(2*CD/128, 2*CR/128, 1), 256, SM128>>>(
        mem_ln, CD, 0, 0,  w_kvproj, CD, 0, 0,  kv, 2*CD, 0, 0,
        2*CR, 2*CD, CD, 1, 1.f,
        nullptr, nullptr, 0, nullptr, 0, nullptr, 0, 0, 0);

    // 13. RoPE on kc (positions mod N); transpose Vc
    rope_kernel<<<2*CR, 512>>>(kv, 2*CD, cosb, sinb, 2*CN, CN);
    transpose_v<<<dim3(2*CN/32, CHD/32, CB*CH), dim3(32,8)>>>(kv + CD, vt, 2*CN, 2*CD);

    // 14. cross scores = qc @ kc^T / 8 + M_hyb
    gemm_mma<128><<<dim3(2*CN/128, CN/128, CB*CH), 256, SM128>>>(
        qc, CD, (long)CN*CD, CHD,
        kv, 2*CD, (long)2*CN*2*CD, CHD,
        scores, 2*CN, (long)CH*CN*2*CN, (long)CN*2*CN,
        CN, 2*CN, CHD, CH, 0.125f,
        nullptr, nullptr, 0, nullptr, 0,
        M_hyb, 2*CN, (long)CN*2*CN, 16);

    // 15. softmax over 2N
    softmax_kernel<<<CB*CH*CN, 256>>>(scores, 2*CN);

    // 16. O = P @ Vc
    gemm_mma<64><<<dim3(1, CN/128, CB*CH), 256, SM64>>>(
        scores, 2*CN, (long)CH*CN*2*CN, (long)CN*2*CN,
        vt, 2*CN, (long)CH*CHD*2*CN, (long)CHD*2*CN,
        attn_o, CD, (long)CN*CD, CHD,
        CN, CHD, 2*CN, CH, 1.f,
        nullptr, nullptr, 0, nullptr, 0, nullptr, 0, 0, 0);

    // 17. x2 = x1 + g_c * (O @ w_cross_out^T)
    gemm_mma<128><<<dim3(CD/128, CR/128, 1), 256, SM128>>>(
        attn_o, CD, 0, 0,  w_cross_out, CD, 0, 0,  x2, CD, 0, 0,
        CR, CD, CD, 1, 1.f,
        nullptr, x1, CD, ada + 5*CD, CD12, nullptr, 0, 0, 4|8);

    // 18. xn = modulate(LN(x2), sh_m, sc_m)
    ln_mod_kernel<<<CR, 256>>>(x2, w_ln_mlp, ada, CD12, 6*CD, 7*CD,
                               xn, CN, CN, 0, 1);

    // 19. h = gelu(xn @ w_mlp1^T + b_mlp1)
    gemm_mma<128><<<dim3(4*CD/128, CR/128, 1), 256, SM128>>>(
        xn, CD, 0, 0,  w_mlp1, CD, 0, 0,  hbuf, 4*CD, 0, 0,
        CR, 4*CD, CD, 1, 1.f,
        b_mlp1, nullptr, 0, nullptr, 0, nullptr, 0, 0, 1|2);

    // 20. out = x2 + g_m * (h @ w_mlp2^T + b_mlp2)
    gemm_mma<128><<<dim3(CD/128, CR/128, 1), 256, SM128>>>(
        hbuf, 4*CD, 0, 0,  w_mlp2, 4*CD, 0, 0,  outp, CD, 0, 0,
        CR, CD, 4*CD, 1, 1.f,
        b_mlp2, x2, CD, ada + 8*CD, CD12, nullptr, 0, 0, 1|4|8);
}